// round 1
// baseline (speedup 1.0000x reference)
#include <cuda_runtime.h>
#include <float.h>

#define Nn    16384
#define Dd    128
#define KK    32
#define BM    128

// smem layout (floats):
//   As [128][129]  transposed A tile (k-major), resident
//   Bs [128][129]  transposed B tile (k-major), per-iter
//   Cs [128][65]   C staging, one 64-col half at a time
//   TV [128][33]   per-row top-32 values, ascending sorted (pad 33 -> conflict-free)
//   TI [128][33]   per-row top-32 indices
#define AS_OFF   0
#define BS_OFF   (128*129)
#define CS_OFF   (2*128*129)
#define TV_OFF   (2*128*129 + 128*65)
#define TI_OFF   (2*128*129 + 128*65 + 128*33)
#define SMEM_FLOATS (2*128*129 + 128*65 + 2*128*33)

__global__ __launch_bounds__(256, 1)
void gsl_topk_kernel(const float* __restrict__ W, float* __restrict__ out)
{
    extern __shared__ float sm[];
    float* As = sm + AS_OFF;
    float* Bs = sm + BS_OFF;
    float* Cs = sm + CS_OFF;
    float* TV = sm + TV_OFF;
    int*   TI = (int*)(sm + TI_OFF);

    const int tid = threadIdx.x;
    const int tx  = tid & 15;   // 16 col groups
    const int ty  = tid >> 4;   // 16 row groups
    const int rb  = blockIdx.x * BM;
    const int r   = tid;        // top-k row owner when r < 128

    // ---- init top-k lists ----
    for (int i = tid; i < 128 * 33; i += 256) { TV[i] = -FLT_MAX; TI[i] = 0; }

    // ---- load A tile transposed: As[k][row] ----
    // lanes -> consecutive k: gmem coalesced; STS banks (k + row) % 32 distinct.
    #pragma unroll 4
    for (int s = 0; s < 64; s++) {
        int idx = tid + 256 * s;
        int k  = idx & 127;
        int rr = idx >> 7;
        As[k * 129 + rr] = W[(rb + rr) * Dd + k];
    }

    float vmin = -FLT_MAX;
    __syncthreads();

    float acc[8][8];

    for (int jt = 0; jt < Nn / BM; jt++) {
        const int jb = jt * BM;

        // ---- load B tile transposed: Bs[k][col] ----
        #pragma unroll 4
        for (int s = 0; s < 64; s++) {
            int idx = tid + 256 * s;
            int k = idx & 127;
            int c = idx >> 7;
            Bs[k * 129 + c] = W[(jb + c) * Dd + k];
        }
        __syncthreads();

        // ---- 128x128x128 FFMA GEMM, 8x8 per thread ----
        // thread rows: ty*8 + i (contiguous),  thread cols: tx + 16*j (strided)
        #pragma unroll
        for (int i = 0; i < 8; i++)
            #pragma unroll
            for (int j = 0; j < 8; j++) acc[i][j] = 0.0f;

        #pragma unroll 4
        for (int k = 0; k < Dd; k++) {
            float a[8], b[8];
            const float* ak = As + k * 129 + ty * 8;
            const float* bk = Bs + k * 129 + tx;
            #pragma unroll
            for (int i = 0; i < 8; i++) a[i] = ak[i];          // broadcast (2 addrs/warp)
            #pragma unroll
            for (int j = 0; j < 8; j++) b[j] = bk[16 * j];     // 16 consecutive banks
            #pragma unroll
            for (int i = 0; i < 8; i++)
                #pragma unroll
                for (int j = 0; j < 8; j++) acc[i][j] += a[i] * b[j];
        }

        // ---- stage + scan in two 64-col halves ----
        #pragma unroll
        for (int h = 0; h < 2; h++) {
            __syncthreads();  // prior scan (or GEMM) done before Cs overwrite
            #pragma unroll
            for (int i = 0; i < 8; i++)
                #pragma unroll
                for (int j = 0; j < 4; j++) {
                    int jj = h * 4 + j;
                    // local col within half = (tx + 16*jj) - h*64 = tx + 16*j
                    Cs[(ty * 8 + i) * 65 + tx + 16 * j] = acc[i][jj];
                }
            __syncthreads();

            if (r < 128) {
                const float* crow = Cs + r * 65;     // banks (r + c) % 32 distinct
                float* tvr = TV + r * 33;
                int*   tir = TI + r * 33;
                #pragma unroll 4
                for (int c = 0; c < 64; c++) {
                    float v = crow[c];
                    if (v > vmin) {
                        int ci = jb + h * 64 + c;
                        int p = 0;
                        while (p < 31 && tvr[p + 1] < v) {
                            tvr[p] = tvr[p + 1];
                            tir[p] = tir[p + 1];
                            p++;
                        }
                        tvr[p] = v;
                        tir[p] = ci;
                        vmin = tvr[0];
                    }
                }
            }
        }
        __syncthreads();  // before Bs refill
    }

    __syncthreads();

    // ---- per-row sort by column index ascending, then emit ----
    if (r < 128) {
        float* tvr = TV + r * 33;
        int*   tir = TI + r * 33;
        for (int s = 1; s < KK; s++) {
            int   ii = tir[s];
            float vv = tvr[s];
            int p = s - 1;
            while (p >= 0 && tir[p] > ii) {
                tir[p + 1] = tir[p];
                tvr[p + 1] = tvr[p];
                p--;
            }
            tir[p + 1] = ii;
            tvr[p + 1] = vv;
        }
        const long long NK = (long long)Nn * KK;
        const long long grow = rb + r;
        float* o = out + grow * KK;
        float growf = (float)grow;
        #pragma unroll
        for (int i = 0; i < KK; i++) {
            o[i]          = growf;            // edge_index[0] : source rows
            o[NK + i]     = (float)tir[i];    // edge_index[1] : sorted cols
            o[2 * NK + i] = tvr[i];           // edge_values
        }
    }
}

extern "C" void kernel_launch(void* const* d_in, const int* in_sizes, int n_in,
                              void* d_out, int out_size)
{
    // inputs: x [N] (unused), W [N*D]; pick W by element count to be robust.
    const float* W = (const float*)d_in[n_in > 1 ? 1 : 0];
    for (int i = 0; i < n_in; i++) {
        if (in_sizes[i] == Nn * Dd) { W = (const float*)d_in[i]; break; }
    }

    size_t smem = (size_t)SMEM_FLOATS * sizeof(float);  // 199168 B
    cudaFuncSetAttribute(gsl_topk_kernel,
                         cudaFuncAttributeMaxDynamicSharedMemorySize, (int)smem);
    gsl_topk_kernel<<<Nn / BM, 256, smem>>>(W, (float*)d_out);
    (void)out_size;
}

// round 5
// speedup vs baseline: 1.0574x; 1.0574x over previous
#include <cuda_runtime.h>
#include <cuda_bf16.h>
#include <cstdint>
#include <float.h>

#define Nn    16384
#define Dd    128
#define KK    32
#define BM    128        // rows per CTA
#define BN    64         // cols per j-tile
#define NT    (Nn / BN)  // 256 j-tiles

// ---------------- precomputed 3-way bf16 split of W ----------------
__device__ uint4 g_h4[Nn * Dd / 8];   // 4 MB each, [row][k] bf16, 8 per uint4
__device__ uint4 g_m4[Nn * Dd / 8];
__device__ uint4 g_l4[Nn * Dd / 8];

__global__ void split_kernel(const float* __restrict__ W)
{
    int g = blockIdx.x * blockDim.x + threadIdx.x;
    int i = g * 8;
    float4 x0 = *(const float4*)(W + i);
    float4 x1 = *(const float4*)(W + i + 4);
    float xv[8] = {x0.x, x0.y, x0.z, x0.w, x1.x, x1.y, x1.z, x1.w};
    union { __nv_bfloat16 b[8]; uint4 v; } h, m, l;
#pragma unroll
    for (int q = 0; q < 8; q++) {
        float x = xv[q];
        __nv_bfloat16 hb = __float2bfloat16(x);
        float r1 = x - __bfloat162float(hb);
        __nv_bfloat16 mb = __float2bfloat16(r1);
        float r2 = r1 - __bfloat162float(mb);
        h.b[q] = hb; m.b[q] = mb; l.b[q] = __float2bfloat16(r2);
    }
    g_h4[g] = h.v; g_m4[g] = m.v; g_l4[g] = l.v;
}

// ---------------- helpers ----------------
__device__ __forceinline__ uint32_t smem_u32(const void* p)
{
    uint32_t a;
    asm("{ .reg .u64 t; cvta.to.shared.u64 t, %1; cvt.u32.u64 %0, t; }" : "=r"(a) : "l"(p));
    return a;
}
__device__ __forceinline__ void ldsm4(uint32_t* r, uint32_t addr)
{
    asm volatile("ldmatrix.sync.aligned.m8n8.x4.shared.b16 {%0,%1,%2,%3}, [%4];"
                 : "=r"(r[0]), "=r"(r[1]), "=r"(r[2]), "=r"(r[3]) : "r"(addr));
}
__device__ __forceinline__ void mma16816(float* c, const uint32_t* a,
                                         uint32_t b0, uint32_t b1)
{
    asm volatile(
        "mma.sync.aligned.m16n8k16.row.col.f32.bf16.bf16.f32 "
        "{%0,%1,%2,%3}, {%4,%5,%6,%7}, {%8,%9}, {%0,%1,%2,%3};"
        : "+f"(c[0]), "+f"(c[1]), "+f"(c[2]), "+f"(c[3])
        : "r"(a[0]), "r"(a[1]), "r"(a[2]), "r"(a[3]), "r"(b0), "r"(b1));
}
__device__ __forceinline__ void cp16(uint32_t dst, const void* src)
{
    asm volatile("cp.async.cg.shared.global [%0], [%1], 16;" :: "r"(dst), "l"(src));
}
#define CP_COMMIT() asm volatile("cp.async.commit_group;" ::: "memory")
#define CP_WAIT1()  asm volatile("cp.async.wait_group 1;" ::: "memory")

// ---------------- SMEM layout (bytes) ----------------
#define SM_A   0u          // 3 mats x 32KB, rows 256B, swizzle u^(row&7)
#define SM_B   98304u      // 2 stages x 3 mats x 8KB ([64 n][64 k], rows 128B)
#define SM_C   147456u     // 128 x 65 f32
#define SM_TV  180736u     // 128*32 f32
#define SM_TI  197120u     // 128*32 i32
#define SM_TOTAL 213504u

__global__ __launch_bounds__(256, 1)
void gsl_hmma_kernel(float* __restrict__ out)
{
    extern __shared__ char sm[];
    const uint32_t smb = smem_u32(sm);
    const int tid = threadIdx.x;
    const int wid = tid >> 5;
    const int lane = tid & 31;
    const int rb = blockIdx.x * BM;

    float* Cs = (float*)(sm + SM_C);
    float* TV = (float*)(sm + SM_TV);
    int*   TI = (int*)(sm + SM_TI);

    // ---- B stage loader: [64 n][64 k] per mat, rows 128B, swizzle u^(n&7) ----
    auto loadB = [&](int nb, int kh, int st) {
#pragma unroll
        for (int s = 0; s < 6; s++) {
            int idx = tid + 256 * s;        // 0..1535
            int mat = idx >> 9;
            int r2  = idx & 511;
            int n   = r2 >> 3;
            int u   = r2 & 7;
            const uint4* base = (mat == 0) ? g_h4 : (mat == 1) ? g_m4 : g_l4;
            uint32_t dst = smb + SM_B + (uint32_t)st * 24576u + (uint32_t)mat * 8192u
                         + (uint32_t)n * 128u + (uint32_t)((u ^ (n & 7)) << 4);
            cp16(dst, base + (nb + n) * 16 + kh * 8 + u);
        }
        CP_COMMIT();
    };

    // prefetch tile 0, both k-halves (slots 0,1)
    loadB(0, 0, 0);
    loadB(0, 1, 1);

    for (int i = tid; i < 128 * 32; i += 256) { TV[i] = -FLT_MAX; TI[i] = 0; }

    // ---- resident A tile: 3 mats, swizzled ----
#pragma unroll
    for (int s = 0; s < 24; s++) {
        int idx = tid + 256 * s;            // 0..6143
        int mat = idx >> 11;
        int r2  = idx & 2047;
        int row = r2 >> 4;
        int u   = r2 & 15;
        const uint4* base = (mat == 0) ? g_h4 : (mat == 1) ? g_m4 : g_l4;
        uint4 v = base[(rb + row) * 16 + u];
        uint32_t off = SM_A + (uint32_t)mat * 32768u + (uint32_t)row * 256u
                     + (uint32_t)((u ^ (row & 7)) << 4);
        *(uint4*)(sm + off) = v;
    }

    // ---- per-lane ldmatrix constants ----
    const int l7 = lane & 7;
    const int b4 = (lane >> 4) & 1;
    const int lrow = l7 + 8 * ((lane >> 3) & 1);   // 0..15
    const int wy = wid >> 2, wx = wid & 3;

    uint32_t abase[4];
#pragma unroll
    for (int i = 0; i < 4; i++)
        abase[i] = smb + SM_A + (uint32_t)(64 * wy + 16 * i + lrow) * 256u;
    const uint32_t bofs = (uint32_t)(16 * wx + lrow) * 128u;

    __syncthreads();   // A tile + init visible

    float vmin = -FLT_MAX;
    float* tvr = TV + tid * 32;
    int*   tir = TI + tid * 32;

    for (int j = 0; j < NT; j++) {
        const int jb = j * BN;
        float c[4][2][4];
#pragma unroll
        for (int i = 0; i < 4; i++)
#pragma unroll
            for (int nh = 0; nh < 2; nh++)
#pragma unroll
                for (int q = 0; q < 4; q++) c[i][nh][q] = 0.0f;

#pragma unroll
        for (int g = 0; g < 2; g++) {
            const int gg = 2 * j + g;
            CP_WAIT1();
            __syncthreads();
            const uint32_t bb = smb + SM_B + (uint32_t)(gg & 1) * 24576u;
#pragma unroll
            for (int kk2 = 0; kk2 < 4; kk2++) {
                const int kk = g * 4 + kk2;
                const uint32_t ca = (uint32_t)(((2 * kk + b4) ^ l7) << 4);
                const uint32_t cb = (uint32_t)(((2 * kk2 + b4) ^ l7) << 4);
                uint32_t ah[4][4], am[4][4], al[4][4], bh[4], bm[4], bl[4];
#pragma unroll
                for (int i = 0; i < 4; i++) {
                    ldsm4(ah[i], abase[i] + ca);
                    ldsm4(am[i], abase[i] + 32768u + ca);
                    ldsm4(al[i], abase[i] + 65536u + ca);
                }
                ldsm4(bh, bb + bofs + cb);
                ldsm4(bm, bb + 8192u + bofs + cb);
                ldsm4(bl, bb + 16384u + bofs + cb);
#pragma unroll
                for (int i = 0; i < 4; i++) {
                    mma16816(c[i][0], ah[i], bh[0], bh[2]);   // h·h
                    mma16816(c[i][1], ah[i], bh[1], bh[3]);
                    mma16816(c[i][0], ah[i], bm[0], bm[2]);   // h·m
                    mma16816(c[i][1], ah[i], bm[1], bm[3]);
                    mma16816(c[i][0], am[i], bh[0], bh[2]);   // m·h
                    mma16816(c[i][1], am[i], bh[1], bh[3]);
                    mma16816(c[i][0], ah[i], bl[0], bl[2]);   // h·l
                    mma16816(c[i][1], ah[i], bl[1], bl[3]);
                    mma16816(c[i][0], al[i], bh[0], bh[2]);   // l·h
                    mma16816(c[i][1], al[i], bh[1], bh[3]);
                    mma16816(c[i][0], am[i], bm[0], bm[2]);   // m·m
                    mma16816(c[i][1], am[i], bm[1], bm[3]);
                }
            }
            __syncthreads();                  // all warps done reading this slot
            int nxt = gg + 2;
            if (nxt < 2 * NT) loadB((nxt >> 1) * BN, nxt & 1, nxt & 1);
            else CP_COMMIT();
        }

        // ---- stage C to smem ----
#pragma unroll
        for (int i = 0; i < 4; i++)
#pragma unroll
            for (int nh = 0; nh < 2; nh++) {
                int row = 64 * wy + 16 * i + (lane >> 2);
                int col = 16 * wx + 8 * nh + 2 * (lane & 3);
                Cs[row * 65 + col]           = c[i][nh][0];
                Cs[row * 65 + col + 1]       = c[i][nh][1];
                Cs[(row + 8) * 65 + col]     = c[i][nh][2];
                Cs[(row + 8) * 65 + col + 1] = c[i][nh][3];
            }
        __syncthreads();

        // ---- fused top-32 scan ----
        if (tid < 128) {
            const float* crow = Cs + tid * 65;   // banks (tid + c) % 32: conflict-free
#pragma unroll 4
            for (int cc = 0; cc < BN; cc++) {
                float v = crow[cc];
                if (v > vmin) {
                    int ci = jb + cc;
                    int p = 0;
                    while (p < 31 && tvr[p + 1] < v) {
                        tvr[p] = tvr[p + 1];
                        tir[p] = tir[p + 1];
                        p++;
                    }
                    tvr[p] = v;
                    tir[p] = ci;
                    vmin = tvr[0];
                }
            }
        }
        __syncthreads();
    }

    // ---- sort by column index ascending + emit ----
    if (tid < 128) {
        for (int s = 1; s < KK; s++) {
            int   ii = tir[s];
            float vv = tvr[s];
            int p = s - 1;
            while (p >= 0 && tir[p] > ii) {
                tir[p + 1] = tir[p];
                tvr[p + 1] = tvr[p];
                p--;
            }
            tir[p + 1] = ii;
            tvr[p + 1] = vv;
        }
        const long long NK = (long long)Nn * KK;
        const long long grow = rb + tid;
        float* o = out + grow * KK;
        float growf = (float)grow;
#pragma unroll
        for (int i = 0; i < KK; i++) {
            o[i]          = growf;
            o[NK + i]     = (float)tir[i];
            o[2 * NK + i] = tvr[i];
        }
    }
}

extern "C" void kernel_launch(void* const* d_in, const int* in_sizes, int n_in,
                              void* d_out, int out_size)
{
    const float* W = (const float*)d_in[n_in > 1 ? 1 : 0];
    for (int i = 0; i < n_in; i++)
        if (in_sizes[i] == Nn * Dd) { W = (const float*)d_in[i]; break; }

    split_kernel<<<Nn * Dd / 8 / 256, 256>>>(W);

    cudaFuncSetAttribute(gsl_hmma_kernel,
                         cudaFuncAttributeMaxDynamicSharedMemorySize, SM_TOTAL);
    gsl_hmma_kernel<<<Nn / BM, 256, SM_TOTAL>>>((float*)d_out);
    (void)out_size;
}